// round 15
// baseline (speedup 1.0000x reference)
#include <cuda_runtime.h>
#include <cuda_fp16.h>
#include <cstdint>

#define B_  8
#define LQ_ 2048
#define LK_ 2048
#define D_  1024

// ---------------------------------------------------------------------------
// Static device scratch (no runtime allocation allowed)
// ---------------------------------------------------------------------------
__device__ __half g_Qh[(size_t)B_ * LQ_ * D_];   // (input*scale) fp16
__device__ __half g_Mh[(size_t)B_ * LK_ * D_];   // memory [LK,D] fp16
__device__ __half g_MTh[(size_t)B_ * D_ * LK_];  // memory^T [D,LK] fp16
__device__ __half g_Ph[(size_t)B_ * LQ_ * LK_];  // probs fp16
__device__ __half g_Sh[(size_t)B_ * LQ_ * LK_];  // fp16 logits (mask NOT applied)

// ---------------------------------------------------------------------------
// Helpers (base sm_103 ISA: cp.async + mbarrier + ldmatrix + mma.sync)
// ---------------------------------------------------------------------------
__device__ __forceinline__ uint32_t smem_u32(const void* p) {
    uint32_t a;
    asm("{ .reg .u64 t; cvta.to.shared.u64 t, %1; cvt.u32.u64 %0, t; }" : "=r"(a) : "l"(p));
    return a;
}

__device__ __forceinline__ void cp16(uint32_t saddr, const void* gaddr) {
    asm volatile("cp.async.cg.shared.global [%0], [%1], 16;\n" :: "r"(saddr), "l"(gaddr));
}

__device__ __forceinline__ void ldsm4(uint32_t* r, uint32_t addr) {
    asm volatile("ldmatrix.sync.aligned.m8n8.x4.shared.b16 {%0,%1,%2,%3}, [%4];"
                 : "=r"(r[0]), "=r"(r[1]), "=r"(r[2]), "=r"(r[3]) : "r"(addr));
}

__device__ __forceinline__ void mma_f32acc(float* c, const uint32_t* a, const uint32_t* b) {
    asm volatile("mma.sync.aligned.m16n8k16.row.col.f32.f16.f16.f32 "
                 "{%0,%1,%2,%3}, {%4,%5,%6,%7}, {%8,%9}, {%0,%1,%2,%3};"
                 : "+f"(c[0]), "+f"(c[1]), "+f"(c[2]), "+f"(c[3])
                 : "r"(a[0]), "r"(a[1]), "r"(a[2]), "r"(a[3]), "r"(b[0]), "r"(b[1]));
}

#define MBAR_INIT(addr, cnt) \
    asm volatile("mbarrier.init.shared.b64 [%0], %1;" :: "r"((uint32_t)(addr)), "r"((uint32_t)(cnt)) : "memory")

#define MBAR_ARRIVE(addr) \
    asm volatile("mbarrier.arrive.shared.b64 _, [%0];" :: "r"((uint32_t)(addr)) : "memory")

// Deferred arrive when this thread's prior cp.asyncs complete.
// .noinc REQUIRED (R10 deadlock without it).
#define CPASYNC_MBAR_ARRIVE_NOINC(addr) \
    asm volatile("cp.async.mbarrier.arrive.noinc.shared.b64 [%0];" :: "r"((uint32_t)(addr)) : "memory")

#define MBAR_WAIT(addr, par) do {                                                    \
    uint32_t _m = (uint32_t)(addr); uint32_t _p = (uint32_t)(par); uint32_t _d;      \
    asm volatile("{\n\t.reg .pred p;\n\t"                                            \
        "mbarrier.try_wait.parity.acquire.cta.shared::cta.b64 p, [%1], %2;\n\t"      \
        "selp.b32 %0, 1, 0, p;\n\t}"                                                 \
        : "=r"(_d) : "r"(_m), "r"(_p) : "memory");                                   \
    if (!_d) {                                                                       \
        asm volatile("{\n\t.reg .pred P1;\n\t"                                       \
            "WL_%=:\n\t"                                                             \
            "mbarrier.try_wait.parity.acquire.cta.shared::cta.b64 P1, [%0], %1, 0x989680;\n\t" \
            "@P1 bra.uni WD_%=;\n\t"                                                 \
            "bra.uni WL_%=;\n\t"                                                     \
            "WD_%=:\n\t}"                                                            \
            :: "r"(_m), "r"(_p) : "memory");                                         \
    }                                                                                \
} while (0)

// ---------------------------------------------------------------------------
// Merged conversion pass:
//   bid < 8192  : qconv  (input*scale -> g_Qh, 8 elems/thread)
//   bid >= 8192 : mconv  (memory -> g_Mh and transposed g_MTh, 32x32 tiles)
// ---------------------------------------------------------------------------
__global__ __launch_bounds__(256) void conv_kernel(const float* __restrict__ in,
                                                   const float* __restrict__ sc,
                                                   const float* __restrict__ mem) {
    __shared__ float tile[32][33];
    const int bid = blockIdx.x;
    if (bid < 8192) {
        size_t i = ((size_t)bid * 256 + threadIdx.x) * 8;
        float4 a = *(const float4*)(in + i);
        float4 b = *(const float4*)(in + i + 4);
        float4 s0 = *(const float4*)(sc + (i & (D_ - 1)));
        float4 s1 = *(const float4*)(sc + ((i + 4) & (D_ - 1)));
        __half h[8] = {__float2half(a.x * s0.x), __float2half(a.y * s0.y),
                       __float2half(a.z * s0.z), __float2half(a.w * s0.w),
                       __float2half(b.x * s1.x), __float2half(b.y * s1.y),
                       __float2half(b.z * s1.z), __float2half(b.w * s1.w)};
        *(uint4*)(g_Qh + i) = *(uint4*)h;
        return;
    }
    const int r  = bid - 8192;              // 16384 tiles: (32 d) x (64 k) x (8 b)
    const int d0 = (r & 31) * 32;
    const int k0 = ((r >> 5) & 63) * 32;
    const int bz = r >> 11;
    const int tx = threadIdx.x & 31;
    const int ty = threadIdx.x >> 5;  // 0..7
    const float* src = mem + (size_t)bz * LK_ * D_;
#pragma unroll
    for (int j = 0; j < 4; j++) {
        int kl = ty + j * 8;
        float v = src[(size_t)(k0 + kl) * D_ + d0 + tx];
        tile[kl][tx] = v;
        g_Mh[(size_t)bz * LK_ * D_ + (size_t)(k0 + kl) * D_ + d0 + tx] = __float2half(v);
    }
    __syncthreads();
#pragma unroll
    for (int j = 0; j < 4; j++) {
        int dl = ty + j * 8;
        g_MTh[(size_t)bz * D_ * LK_ + (size_t)(d0 + dl) * LK_ + k0 + tx] =
            __float2half(tile[tx][dl]);
    }
}

// ---------------------------------------------------------------------------
// PERSISTENT warp-specialized fp16 GEMM, round 15: 2 CTAs/SM.
//   CTA tile 64(M) x 128(N), 8 consumer warps of 32x32 (2M x 4N), 2 producer
//   warps (even/odd global chunk counter q), 4-stage mbarrier ring carried
//   ACROSS tile boundaries (pipeline never drains). __launch_bounds__(320,2):
//   two independent pipelines per SM cover each other's barrier waits and
//   epilogues (R14 profile: tensor=69.8%, occ=1 CTA -> waits uncovered).
//   Consumer regs ~80 (acc 32 + frags 16) fits the 102-reg cap at occ 2.
// Rows padded to 144B (conflict-free ldmatrix, proven R3-R14).
// ---------------------------------------------------------------------------
#define ROWB  144
#define NSTAGE 4
#define SMEM_STAGE0 1024
#define BM 64
#define BN 128
#define STG_A (BM * ROWB)                         // 9216
#define STG_B (BN * ROWB)                         // 18432
#define STAGE_BYTES (STG_A + STG_B)               // 27648
#define GEMM_SMEM (SMEM_STAGE0 + NSTAGE * STAGE_BYTES)  // 111616
#define NPERSIST 304

template <bool QK>
__global__ __launch_bounds__(320, 2) void gemm_kernel(float* __restrict__ outp) {
    constexpr int KDIM = QK ? D_ : LK_;      // contraction length
    constexpr int NDIM = QK ? LK_ : D_;      // output columns / B rows
    constexpr int NC   = KDIM / 64;          // K chunks per tile
    constexpr int NT   = NDIM / BN;          // tiles along N
    constexpr int MT   = LQ_ / BM;           // tiles along M
    constexpr int NTILES = B_ * MT * NT;     // QK 4096, PV 2048

    extern __shared__ char smem_raw[];
    const uint32_t sb = smem_u32(smem_raw);

    const int t    = threadIdx.x;
    const int lane = t & 31;
    const int w    = t >> 5;                 // 0..9
    const int nCTA = gridDim.x;

    if (t == 0) {
#pragma unroll
        for (int s = 0; s < NSTAGE; s++) {
            MBAR_INIT(sb + s * 8, 32);       // full: 32 deferred producer arrivals
            MBAR_INIT(sb + 32 + s * 8, 8);   // empty: 8 consumer lane-0 arrivals
        }
    }
    __syncthreads();

    if (w >= 8) {
        // ---------- producer warps: handle chunks with (q&1)==(w-8) ----------
        const int sel = w - 8;
        int q = 0;
        for (int tile = blockIdx.x; tile < NTILES; tile += nCTA) {
            const int nx = tile % NT;
            const int my = (tile / NT) % MT;
            const int b  = tile / (NT * MT);
            const __half* Ap = (QK ? g_Qh : g_Ph)
                               + ((size_t)b * LQ_ + my * BM) * KDIM;
            const __half* Bp = (QK ? g_Mh : g_MTh)
                               + ((size_t)b * NDIM + nx * BN) * KDIM;
            for (int c = 0; c < NC; c++, q++) {
                if ((q & 1) != sel) continue;
                const int s = q & 3;
                if (q >= NSTAGE) {
                    MBAR_WAIT(sb + 32 + s * 8, ((q - NSTAGE) >> 2) & 1);
                }
                const uint32_t st = sb + SMEM_STAGE0 + s * STAGE_BYTES;
                const int koff = c * 64;
                // A: BM rows x 8 x 16B  (BM/4 per lane)
#pragma unroll
                for (int i = 0; i < BM / 4; i++) {
                    int id  = lane + (i << 5);
                    int row = id >> 3, ch = id & 7;
                    cp16(st + (uint32_t)(row * ROWB + ch * 16),
                         Ap + (size_t)row * KDIM + koff + ch * 8);
                }
                // B: BN rows x 8 x 16B  (BN/4 per lane)
#pragma unroll
                for (int i = 0; i < BN / 4; i++) {
                    int id  = lane + (i << 5);
                    int row = id >> 3, ch = id & 7;
                    cp16(st + STG_A + (uint32_t)(row * ROWB + ch * 16),
                         Bp + (size_t)row * KDIM + koff + ch * 8);
                }
                CPASYNC_MBAR_ARRIVE_NOINC(sb + s * 8);
            }
        }
        return;
    }

    // ---------------- consumer warps (0..7): 32x32 tiles, 2M x 4N ----------------
    const int wm = (w >> 2) * 32;    // warp M origin
    const int wn = (w & 3) * 32;     // warp N origin

    const int a_row   = wm + (lane & 15);
    const int a_khalf = lane >> 4;                       // 0/1 -> k+0 / k+8
    const int b_row   = wn + (lane & 7) + ((lane >> 4) << 3);
    const int b_khalf = (lane >> 3) & 1;

    int q = 0;
    for (int tile = blockIdx.x; tile < NTILES; tile += nCTA) {
        const int nx = tile % NT;
        const int my = (tile / NT) % MT;
        const int b  = tile / (NT * MT);
        const int m0 = my * BM;
        const int n0 = nx * BN;

        float acc[2][4][4];
#pragma unroll
        for (int i = 0; i < 2; i++)
#pragma unroll
            for (int j = 0; j < 4; j++)
#pragma unroll
                for (int k = 0; k < 4; k++) acc[i][j][k] = 0.0f;

        for (int c = 0; c < NC; c++, q++) {
            const int s = q & 3;
            MBAR_WAIT(sb + s * 8, (q >> 2) & 1);     // wait full[s] (acquire)

            const uint32_t stA = sb + SMEM_STAGE0 + s * STAGE_BYTES;
            const uint32_t stB = stA + STG_A;
            const uint32_t aBase = stA + (uint32_t)(a_row * ROWB + a_khalf * 16);
            const uint32_t bBase = stB + (uint32_t)(b_row * ROWB + b_khalf * 16);

#pragma unroll
            for (int k16 = 0; k16 < 4; k16++) {
                uint32_t af[2][4], bf[2][4];
                const uint32_t ao = aBase + (uint32_t)(k16 * 32);
                const uint32_t bo = bBase + (uint32_t)(k16 * 32);
#pragma unroll
                for (int j = 0; j < 2; j++) ldsm4(bf[j], bo + j * (16 * ROWB));
#pragma unroll
                for (int i = 0; i < 2; i++) ldsm4(af[i], ao + i * (16 * ROWB));

                // Early release: stage dead to this warp after its last LDSM.
                if (k16 == 3 && lane == 0) MBAR_ARRIVE(sb + 32 + s * 8);

#pragma unroll
                for (int i = 0; i < 2; i++)
#pragma unroll
                    for (int jj = 0; jj < 4; jj++)
                        mma_f32acc(acc[i][jj], af[i], &bf[jj >> 1][(jj & 1) * 2]);
            }
        }

        // ---- per-tile epilogue (overlaps producers' next-tile prefetch) ----
#pragma unroll
        for (int i = 0; i < 2; i++) {
            const int r0 = m0 + wm + i * 16 + (lane >> 2);
#pragma unroll
            for (int jj = 0; jj < 4; jj++) {
                const int col = n0 + wn + jj * 8 + (lane & 3) * 2;
                if (QK) {
                    __half* Crow = g_Sh + (size_t)b * LQ_ * LK_;
                    *(__half2*)(Crow + (size_t)r0 * NDIM + col) =
                        __floats2half2_rn(acc[i][jj][0], acc[i][jj][1]);
                    *(__half2*)(Crow + (size_t)(r0 + 8) * NDIM + col) =
                        __floats2half2_rn(acc[i][jj][2], acc[i][jj][3]);
                } else {
                    float* Crow = outp + (size_t)b * LQ_ * D_;
                    *(float2*)(Crow + (size_t)r0 * NDIM + col) =
                        make_float2(acc[i][jj][0], acc[i][jj][1]);
                    *(float2*)(Crow + (size_t)(r0 + 8) * NDIM + col) =
                        make_float2(acc[i][jj][2], acc[i][jj][3]);
                }
            }
        }
    }
}

// ---------------------------------------------------------------------------
// Softmax: fp16 logits + mask (L2-resident) -> fp16 probability row
// ---------------------------------------------------------------------------
__global__ __launch_bounds__(256) void softmax_kernel(const float* __restrict__ mask) {
    const size_t row = blockIdx.x;
    const __half* p = g_Sh + row * LK_;
    const float* mrow = mask + (row >> 11) * LK_;   // row/LQ_ = batch
    const int tid = threadIdx.x;

    uint4 raw = *(const uint4*)(p + tid * 8);
    const __half2* hp = (const __half2*)&raw;
    float v[8];
#pragma unroll
    for (int j = 0; j < 4; j++) {
        float2 f = __half22float2(hp[j]);
        v[2 * j] = f.x; v[2 * j + 1] = f.y;
    }
    float4 mk0 = *(const float4*)(mrow + tid * 8);
    float4 mk1 = *(const float4*)(mrow + tid * 8 + 4);
    v[0] -= 1e30f * mk0.x; v[1] -= 1e30f * mk0.y;
    v[2] -= 1e30f * mk0.z; v[3] -= 1e30f * mk0.w;
    v[4] -= 1e30f * mk1.x; v[5] -= 1e30f * mk1.y;
    v[6] -= 1e30f * mk1.z; v[7] -= 1e30f * mk1.w;

    float m = v[0];
#pragma unroll
    for (int j = 1; j < 8; j++) m = fmaxf(m, v[j]);
#pragma unroll
    for (int o = 16; o > 0; o >>= 1) m = fmaxf(m, __shfl_xor_sync(0xffffffffu, m, o));

    __shared__ float red[8];
    const int warp = tid >> 5;
    if ((tid & 31) == 0) red[warp] = m;
    __syncthreads();
    m = red[0];
#pragma unroll
    for (int i = 1; i < 8; i++) m = fmaxf(m, red[i]);

    float s = 0.0f;
#pragma unroll
    for (int j = 0; j < 8; j++) { v[j] = __expf(v[j] - m); s += v[j]; }
#pragma unroll
    for (int o = 16; o > 0; o >>= 1) s += __shfl_xor_sync(0xffffffffu, s, o);

    __syncthreads();
    if ((tid & 31) == 0) red[warp] = s;
    __syncthreads();
    s = ((red[0] + red[1]) + (red[2] + red[3])) + ((red[4] + red[5]) + (red[6] + red[7]));

    const float inv = 1.0f / s;
    __half h[8];
#pragma unroll
    for (int j = 0; j < 8; j++) h[j] = __float2half(v[j] * inv);
    *(uint4*)(g_Ph + row * LK_ + tid * 8) = *(uint4*)h;
}

// ---------------------------------------------------------------------------
// inputs: 0=input 1=memory 2=mask 3=w_input (cancels in softmax) 4=dot_scale
// ---------------------------------------------------------------------------
extern "C" void kernel_launch(void* const* d_in, const int* in_sizes, int n_in,
                              void* d_out, int out_size) {
    const float* input     = (const float*)d_in[0];
    const float* memory    = (const float*)d_in[1];
    const float* mask      = (const float*)d_in[2];
    const float* dot_scale = (const float*)d_in[4];
    float* out = (float*)d_out;

    cudaFuncSetAttribute(gemm_kernel<true>,  cudaFuncAttributeMaxDynamicSharedMemorySize, GEMM_SMEM);
    cudaFuncSetAttribute(gemm_kernel<false>, cudaFuncAttributeMaxDynamicSharedMemorySize, GEMM_SMEM);

    conv_kernel<<<8192 + 16384, 256>>>(input, dot_scale, memory);

    gemm_kernel<true><<<NPERSIST, 320, GEMM_SMEM>>>(nullptr);

    softmax_kernel<<<B_ * LQ_, 256>>>(mask);

    gemm_kernel<false><<<NPERSIST, 320, GEMM_SMEM>>>(out);
}

// round 16
// speedup vs baseline: 1.1285x; 1.1285x over previous
#include <cuda_runtime.h>
#include <cuda_fp16.h>
#include <cstdint>

#define B_  8
#define LQ_ 2048
#define LK_ 2048
#define D_  1024

// ---------------------------------------------------------------------------
// Static device scratch (no runtime allocation allowed)
// ---------------------------------------------------------------------------
__device__ __half g_Qh[(size_t)B_ * LQ_ * D_];   // (input*scale) fp16
__device__ __half g_Mh[(size_t)B_ * LK_ * D_];   // memory [LK,D] fp16 (only copy)
__device__ __half g_Ph[(size_t)B_ * LQ_ * LK_];  // probs fp16
__device__ __half g_Sh[(size_t)B_ * LQ_ * LK_];  // fp16 logits (mask NOT applied)

// ---------------------------------------------------------------------------
// Helpers (base sm_103 ISA: cp.async + mbarrier + ldmatrix + mma.sync)
// ---------------------------------------------------------------------------
__device__ __forceinline__ uint32_t smem_u32(const void* p) {
    uint32_t a;
    asm("{ .reg .u64 t; cvta.to.shared.u64 t, %1; cvt.u32.u64 %0, t; }" : "=r"(a) : "l"(p));
    return a;
}

__device__ __forceinline__ void cp16(uint32_t saddr, const void* gaddr) {
    asm volatile("cp.async.cg.shared.global [%0], [%1], 16;\n" :: "r"(saddr), "l"(gaddr));
}

__device__ __forceinline__ void ldsm4(uint32_t* r, uint32_t addr) {
    asm volatile("ldmatrix.sync.aligned.m8n8.x4.shared.b16 {%0,%1,%2,%3}, [%4];"
                 : "=r"(r[0]), "=r"(r[1]), "=r"(r[2]), "=r"(r[3]) : "r"(addr));
}

// transposed variant: loads [k][n]-major 8x8 blocks, yields [n][k] fragments
__device__ __forceinline__ void ldsm4t(uint32_t* r, uint32_t addr) {
    asm volatile("ldmatrix.sync.aligned.m8n8.x4.trans.shared.b16 {%0,%1,%2,%3}, [%4];"
                 : "=r"(r[0]), "=r"(r[1]), "=r"(r[2]), "=r"(r[3]) : "r"(addr));
}

__device__ __forceinline__ void mma_f32acc(float* c, const uint32_t* a, const uint32_t* b) {
    asm volatile("mma.sync.aligned.m16n8k16.row.col.f32.f16.f16.f32 "
                 "{%0,%1,%2,%3}, {%4,%5,%6,%7}, {%8,%9}, {%0,%1,%2,%3};"
                 : "+f"(c[0]), "+f"(c[1]), "+f"(c[2]), "+f"(c[3])
                 : "r"(a[0]), "r"(a[1]), "r"(a[2]), "r"(a[3]), "r"(b[0]), "r"(b[1]));
}

#define MBAR_INIT(addr, cnt) \
    asm volatile("mbarrier.init.shared.b64 [%0], %1;" :: "r"((uint32_t)(addr)), "r"((uint32_t)(cnt)) : "memory")

#define MBAR_ARRIVE(addr) \
    asm volatile("mbarrier.arrive.shared.b64 _, [%0];" :: "r"((uint32_t)(addr)) : "memory")

// Deferred arrive when this thread's prior cp.asyncs complete.
// .noinc REQUIRED (R10 deadlock without it).
#define CPASYNC_MBAR_ARRIVE_NOINC(addr) \
    asm volatile("cp.async.mbarrier.arrive.noinc.shared.b64 [%0];" :: "r"((uint32_t)(addr)) : "memory")

#define MBAR_WAIT(addr, par) do {                                                    \
    uint32_t _m = (uint32_t)(addr); uint32_t _p = (uint32_t)(par); uint32_t _d;      \
    asm volatile("{\n\t.reg .pred p;\n\t"                                            \
        "mbarrier.try_wait.parity.acquire.cta.shared::cta.b64 p, [%1], %2;\n\t"      \
        "selp.b32 %0, 1, 0, p;\n\t}"                                                 \
        : "=r"(_d) : "r"(_m), "r"(_p) : "memory");                                   \
    if (!_d) {                                                                       \
        asm volatile("{\n\t.reg .pred P1;\n\t"                                       \
            "WL_%=:\n\t"                                                             \
            "mbarrier.try_wait.parity.acquire.cta.shared::cta.b64 P1, [%0], %1, 0x989680;\n\t" \
            "@P1 bra.uni WD_%=;\n\t"                                                 \
            "bra.uni WL_%=;\n\t"                                                     \
            "WD_%=:\n\t}"                                                            \
            :: "r"(_m), "r"(_p) : "memory");                                         \
    }                                                                                \
} while (0)

// ---------------------------------------------------------------------------
// Conversion pass (pure elementwise now -- no transpose needed):
//   bid < 8192  : g_Qh = half(input * dot_scale)
//   bid >= 8192 : g_Mh = half(memory)
// ---------------------------------------------------------------------------
__global__ __launch_bounds__(256) void conv_kernel(const float* __restrict__ in,
                                                   const float* __restrict__ sc,
                                                   const float* __restrict__ mem) {
    const int bid = blockIdx.x;
    if (bid < 8192) {
        size_t i = ((size_t)bid * 256 + threadIdx.x) * 8;
        float4 a = *(const float4*)(in + i);
        float4 b = *(const float4*)(in + i + 4);
        float4 s0 = *(const float4*)(sc + (i & (D_ - 1)));
        float4 s1 = *(const float4*)(sc + ((i + 4) & (D_ - 1)));
        __half h[8] = {__float2half(a.x * s0.x), __float2half(a.y * s0.y),
                       __float2half(a.z * s0.z), __float2half(a.w * s0.w),
                       __float2half(b.x * s1.x), __float2half(b.y * s1.y),
                       __float2half(b.z * s1.z), __float2half(b.w * s1.w)};
        *(uint4*)(g_Qh + i) = *(uint4*)h;
    } else {
        size_t i = ((size_t)(bid - 8192) * 256 + threadIdx.x) * 8;
        float4 a = *(const float4*)(mem + i);
        float4 b = *(const float4*)(mem + i + 4);
        __half h[8] = {__float2half(a.x), __float2half(a.y),
                       __float2half(a.z), __float2half(a.w),
                       __float2half(b.x), __float2half(b.y),
                       __float2half(b.z), __float2half(b.w)};
        *(uint4*)(g_Mh + i) = *(uint4*)h;
    }
}

// ---------------------------------------------------------------------------
// PERSISTENT warp-specialized fp16 GEMM (fp32 accumulate), round 16:
//   R14 base (proven 398us): grid 152 CTAs, per-CTA global chunk counter q,
//   mbarrier ring carried across tiles, 2 producers (even/odd q), early
//   empty-release, QK 128x256 / PV 128x128.
//   NEW: PV's B tile is stored K-MAJOR (64 k-rows x 256B from g_Mh) and
//   fragments come via ldmatrix.x4.trans -> g_MTh (transposed copy) removed.
//   PV ring deepened to 6 stages (stage shrank to 35KB).
// A rows padded to 144B; PV B rows 272B: r*272 mod 128 = r*16 mod 128 walks
// all 8 16B banks over 8 rows -> conflict-free ldmatrix, 16B-aligned.
// ---------------------------------------------------------------------------
#define ROWB  144
#define ROWBT 272
#define SMEM_STAGE0 1024
#define NPERSIST 152

template <bool QK>
__global__ __launch_bounds__(320, 1) void gemm_kernel(float* __restrict__ outp) {
    constexpr int KDIM = QK ? D_ : LK_;      // contraction length
    constexpr int NDIM = QK ? LK_ : D_;      // output columns
    constexpr int BN   = QK ? 256 : 128;     // CTA N tile
    constexpr int NC   = KDIM / 64;          // K chunks per tile
    constexpr int MI   = QK ? 4 : 2;         // warp M sub-tiles (of 16)
    constexpr int NS   = QK ? 4 : 6;         // ring depth
    constexpr int NT   = NDIM / BN;
    constexpr int MT   = LQ_ / 128;
    constexpr int NTILES = B_ * MT * NT;     // 1024 both
    constexpr int STG_A = 128 * ROWB;                         // 18432
    constexpr int STG_B = QK ? BN * ROWB : 64 * ROWBT;        // 36864 / 17408
    constexpr int STAGE_BYTES = STG_A + STG_B;

    extern __shared__ char smem_raw[];
    const uint32_t sb = smem_u32(smem_raw);

    const int t    = threadIdx.x;
    const int lane = t & 31;
    const int w    = t >> 5;                 // 0..9
    const int nCTA = gridDim.x;

    if (t == 0) {
#pragma unroll
        for (int s = 0; s < NS; s++) {
            MBAR_INIT(sb + s * 8, 32);        // full: deferred producer arrivals
            MBAR_INIT(sb + 64 + s * 8, 8);    // empty: 8 consumer lane-0 arrivals
        }
    }
    __syncthreads();

    if (w >= 8) {
        // ---------- producer warps: handle chunks with (q&1)==(w-8) ----------
        const int sel = w - 8;
        int q = 0;
        for (int tile = blockIdx.x; tile < NTILES; tile += nCTA) {
            const int nx = tile % NT;
            const int my = (tile / NT) % MT;
            const int b  = tile / (NT * MT);
            const __half* Ap = (QK ? g_Qh : g_Ph)
                               + ((size_t)b * LQ_ + my * 128) * KDIM;
            // QK: B rows along N (K-contiguous). PV: B rows along K from g_Mh.
            const __half* Bp = QK
                ? (g_Mh + ((size_t)b * NDIM + nx * BN) * KDIM)
                : (g_Mh + (size_t)b * LK_ * D_ + nx * BN);
            for (int c = 0; c < NC; c++, q++) {
                if ((q & 1) != sel) continue;
                const int s = q % NS;
                if (q >= NS) {
                    MBAR_WAIT(sb + 64 + s * 8, ((q - NS) / NS) & 1);
                }
                const uint32_t st = sb + SMEM_STAGE0 + s * STAGE_BYTES;
                const int koff = c * 64;
                // A: 128 rows x 8 x 16B (32/lane)
#pragma unroll
                for (int i = 0; i < 32; i++) {
                    int id  = lane + (i << 5);
                    int row = id >> 3, ch = id & 7;
                    cp16(st + (uint32_t)(row * ROWB + ch * 16),
                         Ap + (size_t)row * KDIM + koff + ch * 8);
                }
                if (QK) {
                    // B: 256 n-rows x 8 x 16B (64/lane)
#pragma unroll
                    for (int i = 0; i < 64; i++) {
                        int id  = lane + (i << 5);
                        int row = id >> 3, ch = id & 7;
                        cp16(st + STG_A + (uint32_t)(row * ROWB + ch * 16),
                             Bp + (size_t)row * KDIM + koff + ch * 8);
                    }
                } else {
                    // B: 64 k-rows x 16 x 16B (32/lane), k-major from g_Mh
#pragma unroll
                    for (int i = 0; i < 32; i++) {
                        int id  = lane + (i << 5);
                        int row = id >> 4, ch = id & 15;
                        cp16(st + STG_A + (uint32_t)(row * ROWBT + ch * 16),
                             Bp + (size_t)(koff + row) * D_ + ch * 8);
                    }
                }
                CPASYNC_MBAR_ARRIVE_NOINC(sb + s * 8);
            }
        }
        return;
    }

    // ---------------- consumer warps (0..7) ----------------
    const int wm = QK ? (w >> 2) * 64 : (w >> 1) * 32;   // warp M origin
    const int wn = QK ? (w & 3) * 64 : (w & 1) * 64;     // warp N origin

    const int a_row   = wm + (lane & 15);
    const int a_khalf = lane >> 4;
    // QK B addressing (n-major rows)
    const int b_row   = wn + (lane & 7) + ((lane >> 4) << 3);
    const int b_khalf = (lane >> 3) & 1;
    // PV B addressing (k-major rows, ldmatrix.trans):
    //   matrix m = lane>>3: k-sub = (m&1)*8, n-sub = (m>>1)*8; row r = lane&7
    const uint32_t bt_lane = (uint32_t)(((((lane >> 3) & 1) * 8) + (lane & 7)) * ROWBT
                                        + (lane >> 4) * 16);

    int q = 0;
    for (int tile = blockIdx.x; tile < NTILES; tile += nCTA) {
        const int nx = tile % NT;
        const int my = (tile / NT) % MT;
        const int b  = tile / (NT * MT);
        const int m0 = my * 128;
        const int n0 = nx * BN;

        float acc[MI][8][4];
#pragma unroll
        for (int i = 0; i < MI; i++)
#pragma unroll
            for (int j = 0; j < 8; j++)
#pragma unroll
                for (int k = 0; k < 4; k++) acc[i][j][k] = 0.0f;

        for (int c = 0; c < NC; c++, q++) {
            const int s = q % NS;
            MBAR_WAIT(sb + s * 8, (q / NS) & 1);     // wait full[s] (acquire)

            const uint32_t stA = sb + SMEM_STAGE0 + s * STAGE_BYTES;
            const uint32_t stB = stA + STG_A;
            const uint32_t aBase = stA + (uint32_t)(a_row * ROWB + a_khalf * 16);
            const uint32_t bBaseQK = stB + (uint32_t)(b_row * ROWB + b_khalf * 16);
            const uint32_t bBasePV = stB + bt_lane + (uint32_t)(wn * 2);

#pragma unroll
            for (int k16 = 0; k16 < 4; k16++) {
                uint32_t af[MI][4], bf[4][4];
                const uint32_t ao = aBase + (uint32_t)(k16 * 32);
                if (QK) {
                    const uint32_t bo = bBaseQK + (uint32_t)(k16 * 32);
#pragma unroll
                    for (int j = 0; j < 4; j++) ldsm4(bf[j], bo + j * (16 * ROWB));
                } else {
                    const uint32_t bo = bBasePV + (uint32_t)(k16 * (16 * ROWBT));
#pragma unroll
                    for (int j = 0; j < 4; j++) ldsm4t(bf[j], bo + j * 32);
                }
#pragma unroll
                for (int i = 0; i < MI; i++) ldsm4(af[i], ao + i * (16 * ROWB));

                // Early release: stage dead to this warp after its last LDSM.
                if (k16 == 3 && lane == 0) MBAR_ARRIVE(sb + 64 + s * 8);

#pragma unroll
                for (int i = 0; i < MI; i++)
#pragma unroll
                    for (int jj = 0; jj < 8; jj++)
                        mma_f32acc(acc[i][jj], af[i], &bf[jj >> 1][(jj & 1) * 2]);
            }
        }

        // ---- per-tile epilogue (overlaps producers' next-tile prefetch) ----
#pragma unroll
        for (int i = 0; i < MI; i++) {
            const int r0 = m0 + wm + i * 16 + (lane >> 2);
#pragma unroll
            for (int jj = 0; jj < 8; jj++) {
                const int col = n0 + wn + jj * 8 + (lane & 3) * 2;
                if (QK) {
                    __half* Crow = g_Sh + (size_t)b * LQ_ * LK_;
                    *(__half2*)(Crow + (size_t)r0 * NDIM + col) =
                        __floats2half2_rn(acc[i][jj][0], acc[i][jj][1]);
                    *(__half2*)(Crow + (size_t)(r0 + 8) * NDIM + col) =
                        __floats2half2_rn(acc[i][jj][2], acc[i][jj][3]);
                } else {
                    float* Crow = outp + (size_t)b * LQ_ * D_;
                    *(float2*)(Crow + (size_t)r0 * NDIM + col) =
                        make_float2(acc[i][jj][0], acc[i][jj][1]);
                    *(float2*)(Crow + (size_t)(r0 + 8) * NDIM + col) =
                        make_float2(acc[i][jj][2], acc[i][jj][3]);
                }
            }
        }
    }
}

#define GEMM_SMEM_QK (SMEM_STAGE0 + 4 * (128 * ROWB + 256 * ROWB))   // 222208
#define GEMM_SMEM_PV (SMEM_STAGE0 + 6 * (128 * ROWB + 64 * ROWBT))   // 216064

// ---------------------------------------------------------------------------
// Softmax: fp16 logits + mask (L2-resident) -> fp16 probability row
// ---------------------------------------------------------------------------
__global__ __launch_bounds__(256) void softmax_kernel(const float* __restrict__ mask) {
    const size_t row = blockIdx.x;
    const __half* p = g_Sh + row * LK_;
    const float* mrow = mask + (row >> 11) * LK_;   // row/LQ_ = batch
    const int tid = threadIdx.x;

    uint4 raw = *(const uint4*)(p + tid * 8);
    const __half2* hp = (const __half2*)&raw;
    float v[8];
#pragma unroll
    for (int j = 0; j < 4; j++) {
        float2 f = __half22float2(hp[j]);
        v[2 * j] = f.x; v[2 * j + 1] = f.y;
    }
    float4 mk0 = *(const float4*)(mrow + tid * 8);
    float4 mk1 = *(const float4*)(mrow + tid * 8 + 4);
    v[0] -= 1e30f * mk0.x; v[1] -= 1e30f * mk0.y;
    v[2] -= 1e30f * mk0.z; v[3] -= 1e30f * mk0.w;
    v[4] -= 1e30f * mk1.x; v[5] -= 1e30f * mk1.y;
    v[6] -= 1e30f * mk1.z; v[7] -= 1e30f * mk1.w;

    float m = v[0];
#pragma unroll
    for (int j = 1; j < 8; j++) m = fmaxf(m, v[j]);
#pragma unroll
    for (int o = 16; o > 0; o >>= 1) m = fmaxf(m, __shfl_xor_sync(0xffffffffu, m, o));

    __shared__ float red[8];
    const int warp = tid >> 5;
    if ((tid & 31) == 0) red[warp] = m;
    __syncthreads();
    m = red[0];
#pragma unroll
    for (int i = 1; i < 8; i++) m = fmaxf(m, red[i]);

    float s = 0.0f;
#pragma unroll
    for (int j = 0; j < 8; j++) { v[j] = __expf(v[j] - m); s += v[j]; }
#pragma unroll
    for (int o = 16; o > 0; o >>= 1) s += __shfl_xor_sync(0xffffffffu, s, o);

    __syncthreads();
    if ((tid & 31) == 0) red[warp] = s;
    __syncthreads();
    s = ((red[0] + red[1]) + (red[2] + red[3])) + ((red[4] + red[5]) + (red[6] + red[7]));

    const float inv = 1.0f / s;
    __half h[8];
#pragma unroll
    for (int j = 0; j < 8; j++) h[j] = __float2half(v[j] * inv);
    *(uint4*)(g_Ph + row * LK_ + tid * 8) = *(uint4*)h;
}

// ---------------------------------------------------------------------------
// inputs: 0=input 1=memory 2=mask 3=w_input (cancels in softmax) 4=dot_scale
// ---------------------------------------------------------------------------
extern "C" void kernel_launch(void* const* d_in, const int* in_sizes, int n_in,
                              void* d_out, int out_size) {
    const float* input     = (const float*)d_in[0];
    const float* memory    = (const float*)d_in[1];
    const float* mask      = (const float*)d_in[2];
    const float* dot_scale = (const float*)d_in[4];
    float* out = (float*)d_out;

    cudaFuncSetAttribute(gemm_kernel<true>,  cudaFuncAttributeMaxDynamicSharedMemorySize, GEMM_SMEM_QK);
    cudaFuncSetAttribute(gemm_kernel<false>, cudaFuncAttributeMaxDynamicSharedMemorySize, GEMM_SMEM_PV);

    conv_kernel<<<8192 + 8192, 256>>>(input, dot_scale, memory);

    gemm_kernel<true><<<NPERSIST, 320, GEMM_SMEM_QK>>>(nullptr);

    softmax_kernel<<<B_ * LQ_, 256>>>(mask);

    gemm_kernel<false><<<NPERSIST, 320, GEMM_SMEM_PV>>>(out);
}

// round 17
// speedup vs baseline: 1.1478x; 1.0171x over previous
#include <cuda_runtime.h>
#include <cuda_fp16.h>
#include <cstdint>

#define B_  8
#define LQ_ 2048
#define LK_ 2048
#define D_  1024

// ---------------------------------------------------------------------------
// Static device scratch (no runtime allocation allowed)
// ---------------------------------------------------------------------------
__device__ __half g_Qh[(size_t)B_ * LQ_ * D_];   // (input*scale) fp16
__device__ __half g_Mh[(size_t)B_ * LK_ * D_];   // memory [LK,D] fp16 (only copy)
__device__ __half g_Ph[(size_t)B_ * LQ_ * LK_];  // probs fp16
__device__ __half g_Sh[(size_t)B_ * LQ_ * LK_];  // fp16 logits (mask NOT applied)

// ---------------------------------------------------------------------------
// Helpers (base sm_103 ISA: cp.async + mbarrier + ldmatrix + mma.sync)
// ---------------------------------------------------------------------------
__device__ __forceinline__ uint32_t smem_u32(const void* p) {
    uint32_t a;
    asm("{ .reg .u64 t; cvta.to.shared.u64 t, %1; cvt.u32.u64 %0, t; }" : "=r"(a) : "l"(p));
    return a;
}

__device__ __forceinline__ void cp16(uint32_t saddr, const void* gaddr) {
    asm volatile("cp.async.cg.shared.global [%0], [%1], 16;\n" :: "r"(saddr), "l"(gaddr));
}

__device__ __forceinline__ void ldsm4(uint32_t* r, uint32_t addr) {
    asm volatile("ldmatrix.sync.aligned.m8n8.x4.shared.b16 {%0,%1,%2,%3}, [%4];"
                 : "=r"(r[0]), "=r"(r[1]), "=r"(r[2]), "=r"(r[3]) : "r"(addr));
}

// transposed variant: loads [k][n]-major 8x8 blocks, yields [n][k] fragments
__device__ __forceinline__ void ldsm4t(uint32_t* r, uint32_t addr) {
    asm volatile("ldmatrix.sync.aligned.m8n8.x4.trans.shared.b16 {%0,%1,%2,%3}, [%4];"
                 : "=r"(r[0]), "=r"(r[1]), "=r"(r[2]), "=r"(r[3]) : "r"(addr));
}

__device__ __forceinline__ void mma_f32acc(float* c, const uint32_t* a, const uint32_t* b) {
    asm volatile("mma.sync.aligned.m16n8k16.row.col.f32.f16.f16.f32 "
                 "{%0,%1,%2,%3}, {%4,%5,%6,%7}, {%8,%9}, {%0,%1,%2,%3};"
                 : "+f"(c[0]), "+f"(c[1]), "+f"(c[2]), "+f"(c[3])
                 : "r"(a[0]), "r"(a[1]), "r"(a[2]), "r"(a[3]), "r"(b[0]), "r"(b[1]));
}

#define MBAR_INIT(addr, cnt) \
    asm volatile("mbarrier.init.shared.b64 [%0], %1;" :: "r"((uint32_t)(addr)), "r"((uint32_t)(cnt)) : "memory")

#define MBAR_ARRIVE(addr) \
    asm volatile("mbarrier.arrive.shared.b64 _, [%0];" :: "r"((uint32_t)(addr)) : "memory")

// Deferred arrive when this thread's prior cp.asyncs complete.
// .noinc REQUIRED (R10 deadlock without it).
#define CPASYNC_MBAR_ARRIVE_NOINC(addr) \
    asm volatile("cp.async.mbarrier.arrive.noinc.shared.b64 [%0];" :: "r"((uint32_t)(addr)) : "memory")

#define MBAR_WAIT(addr, par) do {                                                    \
    uint32_t _m = (uint32_t)(addr); uint32_t _p = (uint32_t)(par); uint32_t _d;      \
    asm volatile("{\n\t.reg .pred p;\n\t"                                            \
        "mbarrier.try_wait.parity.acquire.cta.shared::cta.b64 p, [%1], %2;\n\t"      \
        "selp.b32 %0, 1, 0, p;\n\t}"                                                 \
        : "=r"(_d) : "r"(_m), "r"(_p) : "memory");                                   \
    if (!_d) {                                                                       \
        asm volatile("{\n\t.reg .pred P1;\n\t"                                       \
            "WL_%=:\n\t"                                                             \
            "mbarrier.try_wait.parity.acquire.cta.shared::cta.b64 P1, [%0], %1, 0x989680;\n\t" \
            "@P1 bra.uni WD_%=;\n\t"                                                 \
            "bra.uni WL_%=;\n\t"                                                     \
            "WD_%=:\n\t}"                                                            \
            :: "r"(_m), "r"(_p) : "memory");                                         \
    }                                                                                \
} while (0)

// ---------------------------------------------------------------------------
// Conversion pass (pure elementwise):
//   bid < 8192  : g_Qh = half(input * dot_scale)
//   bid >= 8192 : g_Mh = half(memory)
// ---------------------------------------------------------------------------
__global__ __launch_bounds__(256) void conv_kernel(const float* __restrict__ in,
                                                   const float* __restrict__ sc,
                                                   const float* __restrict__ mem) {
    const int bid = blockIdx.x;
    if (bid < 8192) {
        size_t i = ((size_t)bid * 256 + threadIdx.x) * 8;
        float4 a = *(const float4*)(in + i);
        float4 b = *(const float4*)(in + i + 4);
        float4 s0 = *(const float4*)(sc + (i & (D_ - 1)));
        float4 s1 = *(const float4*)(sc + ((i + 4) & (D_ - 1)));
        __half h[8] = {__float2half(a.x * s0.x), __float2half(a.y * s0.y),
                       __float2half(a.z * s0.z), __float2half(a.w * s0.w),
                       __float2half(b.x * s1.x), __float2half(b.y * s1.y),
                       __float2half(b.z * s1.z), __float2half(b.w * s1.w)};
        *(uint4*)(g_Qh + i) = *(uint4*)h;
    } else {
        size_t i = ((size_t)(bid - 8192) * 256 + threadIdx.x) * 8;
        float4 a = *(const float4*)(mem + i);
        float4 b = *(const float4*)(mem + i + 4);
        __half h[8] = {__float2half(a.x), __float2half(a.y),
                       __float2half(a.z), __float2half(a.w),
                       __float2half(b.x), __float2half(b.y),
                       __float2half(b.z), __float2half(b.w)};
        *(uint4*)(g_Mh + i) = *(uint4*)h;
    }
}

// ---------------------------------------------------------------------------
// PERSISTENT warp-specialized fp16 GEMM (fp32 accumulate), round 17:
//   K-CHUNK = 128 (was 64): per-chunk fixed costs (TRYWAIT ~90-150cyc hitting
//   both consumer warps of an SMSP at once, LDSM head latency) are amortized
//   over 2x the MMA work. R16 profile: tensor 66.5%, dead ~450cyc/chunk fixed.
//   QK: 128x256 tile, 2-stage ring (104.4KB/stage).
//   PV: 128x128 tile, 3-stage ring (69.6KB/stage), B k-major + ldmatrix.trans.
//   Grid 152 persistent CTAs, ring carried across tiles, 2 producers
//   (even/odd chunk), early empty-release after last LDSM.
// Rows 256B data padded to 272B: r*272 mod 128 = r*16 mod 128 walks all 8
// 16B banks over 8 rows -> conflict-free ldmatrix, 16B-aligned.
// ---------------------------------------------------------------------------
#define ROWB  272
#define SMEM_STAGE0 1024
#define NPERSIST 152

template <bool QK>
__global__ __launch_bounds__(320, 1) void gemm_kernel(float* __restrict__ outp) {
    constexpr int KDIM = QK ? D_ : LK_;      // contraction length
    constexpr int NDIM = QK ? LK_ : D_;      // output columns
    constexpr int BN   = QK ? 256 : 128;     // CTA N tile
    constexpr int NC   = KDIM / 128;         // K chunks per tile (QK 8, PV 16)
    constexpr int MI   = QK ? 4 : 2;         // warp M sub-tiles (of 16)
    constexpr int NS   = QK ? 2 : 3;         // ring depth
    constexpr int NT   = NDIM / BN;
    constexpr int MT   = LQ_ / 128;
    constexpr int NTILES = B_ * MT * NT;     // 1024 both
    constexpr int STG_A = 128 * ROWB;                         // 34816
    constexpr int STG_B = QK ? 256 * ROWB : 128 * ROWB;       // 69632 / 34816
    constexpr int STAGE_BYTES = STG_A + STG_B;

    extern __shared__ char smem_raw[];
    const uint32_t sb = smem_u32(smem_raw);

    const int t    = threadIdx.x;
    const int lane = t & 31;
    const int w    = t >> 5;                 // 0..9
    const int nCTA = gridDim.x;

    if (t == 0) {
#pragma unroll
        for (int s = 0; s < NS; s++) {
            MBAR_INIT(sb + s * 8, 32);        // full: deferred producer arrivals
            MBAR_INIT(sb + 64 + s * 8, 8);    // empty: 8 consumer lane-0 arrivals
        }
    }
    __syncthreads();

    if (w >= 8) {
        // ---------- producer warps: handle chunks with (q&1)==(w-8) ----------
        const int sel = w - 8;
        int q = 0;
        for (int tile = blockIdx.x; tile < NTILES; tile += nCTA) {
            const int nx = tile % NT;
            const int my = (tile / NT) % MT;
            const int b  = tile / (NT * MT);
            const __half* Ap = (QK ? g_Qh : g_Ph)
                               + ((size_t)b * LQ_ + my * 128) * KDIM;
            const __half* Bp = QK
                ? (g_Mh + ((size_t)b * NDIM + nx * BN) * KDIM)
                : (g_Mh + (size_t)b * LK_ * D_ + nx * BN);
            for (int c = 0; c < NC; c++, q++) {
                if ((q & 1) != sel) continue;
                const int s = q % NS;
                if (q >= NS) {
                    MBAR_WAIT(sb + 64 + s * 8, ((q - NS) / NS) & 1);
                }
                const uint32_t st = sb + SMEM_STAGE0 + s * STAGE_BYTES;
                const int koff = c * 128;
                // A: 128 rows x 16 x 16B (64/lane)
#pragma unroll
                for (int i = 0; i < 64; i++) {
                    int id  = lane + (i << 5);
                    int row = id >> 4, ch = id & 15;
                    cp16(st + (uint32_t)(row * ROWB + ch * 16),
                         Ap + (size_t)row * KDIM + koff + ch * 8);
                }
                if (QK) {
                    // B: 256 n-rows x 16 x 16B (128/lane)
#pragma unroll
                    for (int i = 0; i < 128; i++) {
                        int id  = lane + (i << 5);
                        int row = id >> 4, ch = id & 15;
                        cp16(st + STG_A + (uint32_t)(row * ROWB + ch * 16),
                             Bp + (size_t)row * KDIM + koff + ch * 8);
                    }
                } else {
                    // B: 128 k-rows x 16 x 16B (64/lane), k-major from g_Mh
#pragma unroll
                    for (int i = 0; i < 64; i++) {
                        int id  = lane + (i << 5);
                        int row = id >> 4, ch = id & 15;
                        cp16(st + STG_A + (uint32_t)(row * ROWB + ch * 16),
                             Bp + (size_t)(koff + row) * D_ + ch * 8);
                    }
                }
                CPASYNC_MBAR_ARRIVE_NOINC(sb + s * 8);
            }
        }
        return;
    }

    // ---------------- consumer warps (0..7) ----------------
    const int wm = QK ? (w >> 2) * 64 : (w >> 1) * 32;   // warp M origin
    const int wn = QK ? (w & 3) * 64 : (w & 1) * 64;     // warp N origin

    const int a_row   = wm + (lane & 15);
    const int a_khalf = lane >> 4;
    // QK B addressing (n-major rows)
    const int b_row   = wn + (lane & 7) + ((lane >> 4) << 3);
    const int b_khalf = (lane >> 3) & 1;
    // PV B addressing (k-major rows, ldmatrix.trans)
    const uint32_t bt_lane = (uint32_t)(((((lane >> 3) & 1) * 8) + (lane & 7)) * ROWB
                                        + (lane >> 4) * 16);

    int q = 0;
    for (int tile = blockIdx.x; tile < NTILES; tile += nCTA) {
        const int nx = tile % NT;
        const int my = (tile / NT) % MT;
        const int b  = tile / (NT * MT);
        const int m0 = my * 128;
        const int n0 = nx * BN;

        float acc[MI][8][4];
#pragma unroll
        for (int i = 0; i < MI; i++)
#pragma unroll
            for (int j = 0; j < 8; j++)
#pragma unroll
                for (int k = 0; k < 4; k++) acc[i][j][k] = 0.0f;

        for (int c = 0; c < NC; c++, q++) {
            const int s = q % NS;
            MBAR_WAIT(sb + s * 8, (q / NS) & 1);     // wait full[s] (acquire)

            const uint32_t stA = sb + SMEM_STAGE0 + s * STAGE_BYTES;
            const uint32_t stB = stA + STG_A;
            const uint32_t aBase = stA + (uint32_t)(a_row * ROWB + a_khalf * 16);
            const uint32_t bBaseQK = stB + (uint32_t)(b_row * ROWB + b_khalf * 16);
            const uint32_t bBasePV = stB + bt_lane + (uint32_t)(wn * 2);

#pragma unroll
            for (int k16 = 0; k16 < 8; k16++) {
                uint32_t af[MI][4], bf[4][4];
                const uint32_t ao = aBase + (uint32_t)(k16 * 32);
                if (QK) {
                    const uint32_t bo = bBaseQK + (uint32_t)(k16 * 32);
#pragma unroll
                    for (int j = 0; j < 4; j++) ldsm4(bf[j], bo + j * (16 * ROWB));
                } else {
                    const uint32_t bo = bBasePV + (uint32_t)(k16 * (16 * ROWB));
#pragma unroll
                    for (int j = 0; j < 4; j++) ldsm4t(bf[j], bo + j * 32);
                }
#pragma unroll
                for (int i = 0; i < MI; i++) ldsm4(af[i], ao + i * (16 * ROWB));

                // Early release: stage dead to this warp after its last LDSM.
                if (k16 == 7 && lane == 0) MBAR_ARRIVE(sb + 64 + s * 8);

#pragma unroll
                for (int i = 0; i < MI; i++)
#pragma unroll
                    for (int jj = 0; jj < 8; jj++)
                        mma_f32acc(acc[i][jj], af[i], &bf[jj >> 1][(jj & 1) * 2]);
            }
        }

        // ---- per-tile epilogue (overlaps producers' next-tile prefetch) ----
#pragma unroll
        for (int i = 0; i < MI; i++) {
            const int r0 = m0 + wm + i * 16 + (lane >> 2);
#pragma unroll
            for (int jj = 0; jj < 8; jj++) {
                const int col = n0 + wn + jj * 8 + (lane & 3) * 2;
                if (QK) {
                    __half* Crow = g_Sh + (size_t)b * LQ_ * LK_;
                    *(__half2*)(Crow + (size_t)r0 * NDIM + col) =
                        __floats2half2_rn(acc[i][jj][0], acc[i][jj][1]);
                    *(__half2*)(Crow + (size_t)(r0 + 8) * NDIM + col) =
                        __floats2half2_rn(acc[i][jj][2], acc[i][jj][3]);
                } else {
                    float* Crow = outp + (size_t)b * LQ_ * D_;
                    *(float2*)(Crow + (size_t)r0 * NDIM + col) =
                        make_float2(acc[i][jj][0], acc[i][jj][1]);
                    *(float2*)(Crow + (size_t)(r0 + 8) * NDIM + col) =
                        make_float2(acc[i][jj][2], acc[i][jj][3]);
                }
            }
        }
    }
}

#define GEMM_SMEM_QK (SMEM_STAGE0 + 2 * (128 * ROWB + 256 * ROWB))   // 209920
#define GEMM_SMEM_PV (SMEM_STAGE0 + 3 * (128 * ROWB + 128 * ROWB))   // 209920

// ---------------------------------------------------------------------------
// Softmax: fp16 logits + mask (L2-resident) -> fp16 probability row
// ---------------------------------------------------------------------------
__global__ __launch_bounds__(256) void softmax_kernel(const float* __restrict__ mask) {
    const size_t row = blockIdx.x;
    const __half* p = g_Sh + row * LK_;
    const float* mrow = mask + (row >> 11) * LK_;   // row/LQ_ = batch
    const int tid = threadIdx.x;

    uint4 raw = *(const uint4*)(p + tid * 8);
    const __half2* hp = (const __half2*)&raw;
    float v[8];
#pragma unroll
    for (int j = 0; j < 4; j++) {
        float2 f = __half22float2(hp[j]);
        v[2 * j] = f.x; v[2 * j + 1] = f.y;
    }
    float4 mk0 = *(const float4*)(mrow + tid * 8);
    float4 mk1 = *(const float4*)(mrow + tid * 8 + 4);
    v[0] -= 1e30f * mk0.x; v[1] -= 1e30f * mk0.y;
    v[2] -= 1e30f * mk0.z; v[3] -= 1e30f * mk0.w;
    v[4] -= 1e30f * mk1.x; v[5] -= 1e30f * mk1.y;
    v[6] -= 1e30f * mk1.z; v[7] -= 1e30f * mk1.w;

    float m = v[0];
#pragma unroll
    for (int j = 1; j < 8; j++) m = fmaxf(m, v[j]);
#pragma unroll
    for (int o = 16; o > 0; o >>= 1) m = fmaxf(m, __shfl_xor_sync(0xffffffffu, m, o));

    __shared__ float red[8];
    const int warp = tid >> 5;
    if ((tid & 31) == 0) red[warp] = m;
    __syncthreads();
    m = red[0];
#pragma unroll
    for (int i = 1; i < 8; i++) m = fmaxf(m, red[i]);

    float s = 0.0f;
#pragma unroll
    for (int j = 0; j < 8; j++) { v[j] = __expf(v[j] - m); s += v[j]; }
#pragma unroll
    for (int o = 16; o > 0; o >>= 1) s += __shfl_xor_sync(0xffffffffu, s, o);

    __syncthreads();
    if ((tid & 31) == 0) red[warp] = s;
    __syncthreads();
    s = ((red[0] + red[1]) + (red[2] + red[3])) + ((red[4] + red[5]) + (red[6] + red[7]));

    const float inv = 1.0f / s;
    __half h[8];
#pragma unroll
    for (int j = 0; j < 8; j++) h[j] = __float2half(v[j] * inv);
    *(uint4*)(g_Ph + row * LK_ + tid * 8) = *(uint4*)h;
}

// ---------------------------------------------------------------------------
// inputs: 0=input 1=memory 2=mask 3=w_input (cancels in softmax) 4=dot_scale
// ---------------------------------------------------------------------------
extern "C" void kernel_launch(void* const* d_in, const int* in_sizes, int n_in,
                              void* d_out, int out_size) {
    const float* input     = (const float*)d_in[0];
    const float* memory    = (const float*)d_in[1];
    const float* mask      = (const float*)d_in[2];
    const float* dot_scale = (const float*)d_in[4];
    float* out = (float*)d_out;

    cudaFuncSetAttribute(gemm_kernel<true>,  cudaFuncAttributeMaxDynamicSharedMemorySize, GEMM_SMEM_QK);
    cudaFuncSetAttribute(gemm_kernel<false>, cudaFuncAttributeMaxDynamicSharedMemorySize, GEMM_SMEM_PV);

    conv_kernel<<<8192 + 8192, 256>>>(input, dot_scale, memory);

    gemm_kernel<true><<<NPERSIST, 320, GEMM_SMEM_QK>>>(nullptr);

    softmax_kernel<<<B_ * LQ_, 256>>>(mask);

    gemm_kernel<false><<<NPERSIST, 320, GEMM_SMEM_PV>>>(out);
}